// round 7
// baseline (speedup 1.0000x reference)
#include <cuda_runtime.h>
#include <cuda_bf16.h>

#define NB     65536
#define TILE   32                 // batches per tile (lane = batch)
#define NTILE  (NB / TILE)        // 2048 blocks, one tile each
#define TPB    256                // 8 warps
#define F4ARR  (TILE * 75)        // 2400 float4 per array per tile
#define F4TILE (2 * F4ARR)        // A + Y staged
#define SCRATCHF (8 * TILE * 9)   // 8 warps x 32 batches x 9 partials
#define SMEM_BYTES (F4TILE * 16 + SCRATCHF * 4)   // 76800 + 9216 = 86016 -> 2 blocks/SM

#define LN2      0.69314718055994530942f
#define CLAMP_L2 (-144.26950408889634f)   // -100 / ln2

__device__ float        g_partials[NTILE];
__device__ unsigned int g_counter = 0;

// clamped lg2 (clip at -100/ln2; multiply by ln2 deferred to epilogue)
__device__ __forceinline__ float clog2_(float x) {
    return fmaxf(__log2f(x), CLAMP_L2);
}
// full-precision clipped-log BCE for the 3 category elements (matches reference _bce).
__device__ __forceinline__ float bce1(float p, float y) {
    float lp = fmaxf(__logf(p), -100.0f);
    float lm = fmaxf(__logf(1.0f - p), -100.0f);
    return -(y * lp + (1.0f - y) * lm);
}

__device__ __forceinline__ void cp16(void* dst_smem, const void* src_gmem) {
    unsigned s = (unsigned)__cvta_generic_to_shared(dst_smem);
    asm volatile("cp.async.cg.shared.global [%0], [%1], 16;" :: "r"(s), "l"(src_gmem) : "memory");
}

extern __shared__ float4 smem[];   // [A(2400) Y(2400)] [scratch floats]

__global__ void __launch_bounds__(TPB, 2)
loss_kernel(const float* __restrict__ A, const float* __restrict__ CAT,
            const float* __restrict__ Y, const float* __restrict__ CATL,
            float* __restrict__ out)
{
    const int tid  = threadIdx.x;
    const int w    = tid >> 5;
    const int lane = tid & 31;
    const int tile = blockIdx.x;

    float* scratch = reinterpret_cast<float*>(smem + F4TILE);

    // ---- stage tile: A slice + Y slice (each contiguous 38.4KB) ----
    {
        const float4* gA = reinterpret_cast<const float4*>(A) + (size_t)tile * F4ARR;
        const float4* gY = reinterpret_cast<const float4*>(Y) + (size_t)tile * F4ARR;
        #pragma unroll
        for (int i = 0; i < (F4ARR + TPB - 1) / TPB; ++i) {  // 10 iters
            int idx = i * TPB + tid;
            if (idx < F4ARR) {
                cp16(smem + idx,         gA + idx);
                cp16(smem + F4ARR + idx, gY + idx);
            }
        }
        asm volatile("cp.async.commit_group;" ::: "memory");
        asm volatile("cp.async.wait_group 0;" ::: "memory");
        __syncthreads();
    }

    // ---- partials: lane = batch, warp w covers chunks c = w, w+8, w+16[, 24] ----
    // 300-word batch stride is bank-conflict-free for LDS.128 (12*l mod 32 distinct per phase).
    const float4* a4 = smem + lane * 75;
    const float4* y4 = a4 + F4ARR;

    float acc[3][3] = {{0.f,0.f,0.f},{0.f,0.f,0.f},{0.f,0.f,0.f}};  // lg2-domain
    float slog[3]   = {0.f, 0.f, 0.f};

    #pragma unroll 2
    for (int c = w; c < 25; c += 8) {
        float4 av[3], yv[3];
        #pragma unroll
        for (int s = 0; s < 3; ++s) av[s] = a4[s * 25 + c];
        #pragma unroll
        for (int t = 0; t < 3; ++t) yv[t] = y4[t * 25 + c];

        float4 df[3];
        #pragma unroll
        for (int s = 0; s < 3; ++s) {
            float lp, lm, sl = 0.f;
            lp = clog2_(av[s].x); lm = clog2_(1.0f - av[s].x); df[s].x = lp - lm; sl += lm;
            lp = clog2_(av[s].y); lm = clog2_(1.0f - av[s].y); df[s].y = lp - lm; sl += lm;
            lp = clog2_(av[s].z); lm = clog2_(1.0f - av[s].z); df[s].z = lp - lm; sl += lm;
            lp = clog2_(av[s].w); lm = clog2_(1.0f - av[s].w); df[s].w = lp - lm; sl += lm;
            slog[s] += sl;
        }
        #pragma unroll
        for (int s = 0; s < 3; ++s) {
            #pragma unroll
            for (int t = 0; t < 3; ++t) {
                float a0 = acc[s][t];
                a0 = fmaf(yv[t].x, df[s].x, a0);
                a0 = fmaf(yv[t].y, df[s].y, a0);
                a0 = fmaf(yv[t].z, df[s].z, a0);
                a0 = fmaf(yv[t].w, df[s].w, a0);
                acc[s][t] = a0;
            }
        }
    }

    // publish 9 partials per (warp, batch); slog[s] folded in (C[s][t] adds slog[s] for all t)
    {
        float* my = scratch + (w * TILE + lane) * 9;
        #pragma unroll
        for (int s = 0; s < 3; ++s)
            #pragma unroll
            for (int t = 0; t < 3; ++t)
                my[s * 3 + t] = acc[s][t] + slog[s];
    }
    __syncthreads();

    // ---- epilogue: batch bl = w + 8*lane handled by lanes 0..3 of each warp ----
    float vsum = 0.0f;
    if (lane < 4) {
        const int bl = w + 8 * lane;
        float C[3][3];
        #pragma unroll
        for (int k = 0; k < 9; ++k) {
            float s_ = 0.f;
            #pragma unroll
            for (int wk = 0; wk < 8; ++wk)
                s_ += scratch[(wk * TILE + bl) * 9 + k];
            C[k / 3][k % 3] = -LN2 * s_;     // back to natural-log domain
        }

        // 6 permutations (itertools order); strict < keeps first-min (argmin semantics).
        float best = C[0][0] + C[1][1] + C[2][2];
        int p0 = 0, p1 = 1, p2 = 2;
        float L;
        L = C[0][0] + C[2][1] + C[1][2]; if (L < best) { best = L; p0 = 0; p1 = 2; p2 = 1; }
        L = C[1][0] + C[0][1] + C[2][2]; if (L < best) { best = L; p0 = 1; p1 = 0; p2 = 2; }
        L = C[1][0] + C[2][1] + C[0][2]; if (L < best) { best = L; p0 = 1; p1 = 2; p2 = 0; }
        L = C[2][0] + C[0][1] + C[1][2]; if (L < best) { best = L; p0 = 2; p1 = 0; p2 = 1; }
        L = C[2][0] + C[1][1] + C[0][2]; if (L < best) { best = L; p0 = 2; p1 = 1; p2 = 0; }

        const int gb = tile * TILE + bl;
        float c0 = CAT[3 * gb + 0], c1 = CAT[3 * gb + 1], c2 = CAT[3 * gb + 2];
        float l0 = CATL[3 * gb + 0], l1 = CATL[3 * gb + 1], l2 = CATL[3 * gb + 2];
        float q0 = (p0 == 0) ? c0 : ((p0 == 1) ? c1 : c2);
        float q1 = (p1 == 0) ? c0 : ((p1 == 1) ? c1 : c2);
        float q2 = (p2 == 0) ? c0 : ((p2 == 1) ? c1 : c2);
        float catsum = bce1(q0, l0) + bce1(q1, l1) + bce1(q2, l2);

        vsum = best * (1.0f / 300.0f) * (1.0f / (float)NB)
             + catsum * (1.0f / (3.0f * (float)NB));
    }

    // ---- deterministic block reduction (reuse scratch) ----
    __syncthreads();
    scratch[tid] = vsum;
    __syncthreads();
    #pragma unroll
    for (int off = TPB / 2; off > 0; off >>= 1) {
        if (tid < off) scratch[tid] += scratch[tid + off];
        __syncthreads();
    }

    __shared__ unsigned sticket;
    if (tid == 0) {
        g_partials[blockIdx.x] = scratch[0];
        __threadfence();
        sticket = atomicAdd(&g_counter, 1u);
    }
    __syncthreads();

    // Last block sums all 2048 partials in a fixed-order tree (deterministic), resets counter.
    if (sticket == NTILE - 1) {
        __threadfence();
        float v = 0.f;
        #pragma unroll
        for (int i = 0; i < NTILE / TPB; ++i)       // 8 partials per thread, fixed order
            v += g_partials[tid + i * TPB];
        scratch[tid] = v;
        __syncthreads();
        #pragma unroll
        for (int off = TPB / 2; off > 0; off >>= 1) {
            if (tid < off) scratch[tid] += scratch[tid + off];
            __syncthreads();
        }
        if (tid == 0) {
            out[0] = scratch[0];
            g_counter = 0;                           // self-reset for graph replays
        }
    }
}

extern "C" void kernel_launch(void* const* d_in, const int* in_sizes, int n_in,
                              void* d_out, int out_size)
{
    const float* A    = (const float*)d_in[0]; // assignments        (B,3,10,10)
    const float* CAT  = (const float*)d_in[1]; // category           (B,3)
    const float* Y    = (const float*)d_in[2]; // assignments_labels (B,3,10,10)
    const float* CATL = (const float*)d_in[3]; // category_labels    (B,3)

    cudaFuncSetAttribute(loss_kernel, cudaFuncAttributeMaxDynamicSharedMemorySize, SMEM_BYTES);
    loss_kernel<<<NTILE, TPB, SMEM_BYTES>>>(A, CAT, Y, CATL, (float*)d_out);
}

// round 8
// speedup vs baseline: 1.6380x; 1.6380x over previous
#include <cuda_runtime.h>
#include <cuda_bf16.h>

#define NB    65536
#define BPW   4                    // batches per warp (8 lanes each)
#define WPB   8                    // warps per block
#define TPB   (WPB * 32)
#define NBLK  (NB / (BPW * WPB))   // 2048 blocks

#define LN2      0.69314718055994530942f
#define CLAMP_L2 (-144.26950408889634f)   // -100 / ln2

__device__ float        g_partials[NBLK];
__device__ unsigned int g_counter = 0;

// clamped lg2 (clip at -100/ln2; x ln2 deferred to epilogue) == clip(log(p),-100)/ln2
__device__ __forceinline__ float clog2_(float x) {
    return fmaxf(__log2f(x), CLAMP_L2);
}
__device__ __forceinline__ float bce1(float p, float y) {
    float lp = fmaxf(__logf(p), -100.0f);
    float lm = fmaxf(__logf(1.0f - p), -100.0f);
    return -(y * lp + (1.0f - y) * lm);
}

// One float4 chunk: accumulate df-dots into acc (lg2 domain) and log1mp into slog.
__device__ __forceinline__ void chunk_accum(const float4 av[3], const float4 yv[3],
                                            float acc[3][3], float slog[3])
{
    float4 df[3];
    #pragma unroll
    for (int s = 0; s < 3; ++s) {
        float lp, lm, sl = 0.f;
        lp = clog2_(av[s].x); lm = clog2_(1.0f - av[s].x); df[s].x = lp - lm; sl += lm;
        lp = clog2_(av[s].y); lm = clog2_(1.0f - av[s].y); df[s].y = lp - lm; sl += lm;
        lp = clog2_(av[s].z); lm = clog2_(1.0f - av[s].z); df[s].z = lp - lm; sl += lm;
        lp = clog2_(av[s].w); lm = clog2_(1.0f - av[s].w); df[s].w = lp - lm; sl += lm;
        slog[s] += sl;
    }
    #pragma unroll
    for (int s = 0; s < 3; ++s) {
        #pragma unroll
        for (int t = 0; t < 3; ++t) {
            float a0 = acc[s][t];
            a0 = fmaf(yv[t].x, df[s].x, a0);
            a0 = fmaf(yv[t].y, df[s].y, a0);
            a0 = fmaf(yv[t].z, df[s].z, a0);
            a0 = fmaf(yv[t].w, df[s].w, a0);
            acc[s][t] = a0;
        }
    }
}

__global__ void __launch_bounds__(TPB)
loss_kernel(const float* __restrict__ A, const float* __restrict__ CAT,
            const float* __restrict__ Y, const float* __restrict__ CATL,
            float* __restrict__ out)
{
    const int tid  = threadIdx.x;
    const int lane = tid & 31;
    const int g    = lane >> 3;          // batch within warp-quad (0..3)
    const int r    = lane & 7;           // lane within 8-lane batch group
    const int warp = blockIdx.x * WPB + (tid >> 5);
    const int b    = warp * BPW + g;     // this lane's batch

    // 8-lane group covers chunks c = r, r+8, r+16 (24 chunks); chunk 24 goes to r==0.
    const float4* a4 = reinterpret_cast<const float4*>(A) + (size_t)b * 75;
    const float4* y4 = reinterpret_cast<const float4*>(Y) + (size_t)b * 75;

    float acc[3][3] = {{0.f,0.f,0.f},{0.f,0.f,0.f},{0.f,0.f,0.f}};
    float slog[3]   = {0.f, 0.f, 0.f};

    #pragma unroll
    for (int k = 0; k < 3; ++k) {
        const int c = r + k * 8;
        float4 av[3], yv[3];
        #pragma unroll
        for (int s = 0; s < 3; ++s) { av[s] = a4[s * 25 + c]; yv[s] = y4[s * 25 + c]; }
        chunk_accum(av, yv, acc, slog);
    }
    if (r == 0) {                        // ragged 25th chunk
        float4 av[3], yv[3];
        #pragma unroll
        for (int s = 0; s < 3; ++s) { av[s] = a4[s * 25 + 24]; yv[s] = y4[s * 25 + 24]; }
        chunk_accum(av, yv, acc, slog);
    }

    // Fold slog[s] into each acc[s][t] (C[s][t] = -(dot+slog[s])) -> 9 values to reduce.
    #pragma unroll
    for (int s = 0; s < 3; ++s)
        #pragma unroll
        for (int t = 0; t < 3; ++t)
            acc[s][t] += slog[s];

    // Butterfly over the 8-lane group (xor of lane bits 0..2 stays in-group).
    #pragma unroll
    for (int off = 4; off > 0; off >>= 1)
        #pragma unroll
        for (int s = 0; s < 3; ++s) {
            acc[s][0] += __shfl_xor_sync(0xffffffffu, acc[s][0], off);
            acc[s][1] += __shfl_xor_sync(0xffffffffu, acc[s][1], off);
            acc[s][2] += __shfl_xor_sync(0xffffffffu, acc[s][2], off);
        }

    // Epilogue on lane r==0 of each group (4 concurrent lanes per warp).
    float vsum = 0.0f;
    if (r == 0) {
        float C[3][3];
        #pragma unroll
        for (int s = 0; s < 3; ++s)
            #pragma unroll
            for (int t = 0; t < 3; ++t)
                C[s][t] = -LN2 * acc[s][t];

        // 6 permutations (itertools order); strict < keeps first-min (argmin semantics).
        float best = C[0][0] + C[1][1] + C[2][2];
        int p0 = 0, p1 = 1, p2 = 2;
        float L;
        L = C[0][0] + C[2][1] + C[1][2]; if (L < best) { best = L; p0 = 0; p1 = 2; p2 = 1; }
        L = C[1][0] + C[0][1] + C[2][2]; if (L < best) { best = L; p0 = 1; p1 = 0; p2 = 2; }
        L = C[1][0] + C[2][1] + C[0][2]; if (L < best) { best = L; p0 = 1; p1 = 2; p2 = 0; }
        L = C[2][0] + C[0][1] + C[1][2]; if (L < best) { best = L; p0 = 2; p1 = 0; p2 = 1; }
        L = C[2][0] + C[1][1] + C[0][2]; if (L < best) { best = L; p0 = 2; p1 = 1; p2 = 0; }

        float c0 = CAT[3 * b + 0], c1 = CAT[3 * b + 1], c2 = CAT[3 * b + 2];
        float l0 = CATL[3 * b + 0], l1 = CATL[3 * b + 1], l2 = CATL[3 * b + 2];
        float q0 = (p0 == 0) ? c0 : ((p0 == 1) ? c1 : c2);
        float q1 = (p1 == 0) ? c0 : ((p1 == 1) ? c1 : c2);
        float q2 = (p2 == 0) ? c0 : ((p2 == 1) ? c1 : c2);
        float catsum = bce1(q0, l0) + bce1(q1, l1) + bce1(q2, l2);

        vsum = best * (1.0f / 300.0f) * (1.0f / (float)NB)
             + catsum * (1.0f / (3.0f * (float)NB));
    }

    // ---- deterministic block reduction ----
    __shared__ float sm[TPB];
    sm[tid] = vsum;
    __syncthreads();
    #pragma unroll
    for (int off = TPB / 2; off > 0; off >>= 1) {
        if (tid < off) sm[tid] += sm[tid + off];
        __syncthreads();
    }

    __shared__ unsigned sticket;
    if (tid == 0) {
        g_partials[blockIdx.x] = sm[0];
        __threadfence();
        sticket = atomicAdd(&g_counter, 1u);
    }
    __syncthreads();

    // Last block sums all 2048 partials in fixed order (deterministic), resets counter.
    if (sticket == NBLK - 1) {
        __threadfence();
        float v = 0.f;
        #pragma unroll
        for (int i = 0; i < NBLK / TPB; ++i)     // 8 per thread, fixed order
            v += g_partials[tid + i * TPB];
        sm[tid] = v;
        __syncthreads();
        #pragma unroll
        for (int off = TPB / 2; off > 0; off >>= 1) {
            if (tid < off) sm[tid] += sm[tid + off];
            __syncthreads();
        }
        if (tid == 0) {
            out[0] = sm[0];
            g_counter = 0;                        // self-reset for graph replays
        }
    }
}

extern "C" void kernel_launch(void* const* d_in, const int* in_sizes, int n_in,
                              void* d_out, int out_size)
{
    const float* A    = (const float*)d_in[0]; // assignments        (B,3,10,10)
    const float* CAT  = (const float*)d_in[1]; // category           (B,3)
    const float* Y    = (const float*)d_in[2]; // assignments_labels (B,3,10,10)
    const float* CATL = (const float*)d_in[3]; // category_labels    (B,3)

    loss_kernel<<<NBLK, TPB>>>(A, CAT, Y, CATL, (float*)d_out);
}